// round 13
// baseline (speedup 1.0000x reference)
#include <cuda_runtime.h>
#include <cuda_bf16.h>
#include <cuda_fp16.h>
#include <math.h>
#include <stdint.h>

#define BATCH   4
#define SEQ     2048
#define DMODEL  2048
#define NHEADS  16
#define NKV     4
#define DHEAD   128
#define MTOT    (BATCH * SEQ)          // 8192
#define NKVD    (NKV * DHEAD)          // 512
#define NQKV    (DMODEL + 2 * NKVD)    // 3072

// ---------------- scratch ----------
__device__ __half g_qf[MTOT * DMODEL];                       // roped Q f16
__device__ __half g_kf[MTOT * NKVD];                         // roped K f16
__device__ __half g_vf[MTOT * NKVD];                         // V f16

__device__ __half g_xf[MTOT * DMODEL];                       // x f16
__device__ __half g_of[MTOT * DMODEL];                       // attn out f16
__device__ __half g_wqkv[NQKV * DMODEL];                     // [Wq;Wk;Wv]^T f16
__device__ __half g_wof[DMODEL * DMODEL];

__device__ float g_ropec[SEQ * 64], g_ropes[SEQ * 64];

// ---------------- helpers ---------------------------------------------
__device__ __forceinline__ uint32_t smem_u32(const void* p) {
    uint32_t a;
    asm("{ .reg .u64 t; cvta.to.shared.u64 t, %1; cvt.u32.u64 %0, t; }"
        : "=r"(a) : "l"(p));
    return a;
}
#define SWZ128(o) ((o) ^ (((o) >> 3) & 0x70))

__device__ __forceinline__ void ldsm4(uint32_t& r0, uint32_t& r1,
                                      uint32_t& r2, uint32_t& r3, uint32_t addr) {
    asm volatile("ldmatrix.sync.aligned.m8n8.x4.shared.b16 {%0,%1,%2,%3}, [%4];"
                 : "=r"(r0), "=r"(r1), "=r"(r2), "=r"(r3) : "r"(addr));
}
__device__ __forceinline__ void ldsm4t(uint32_t& r0, uint32_t& r1,
                                       uint32_t& r2, uint32_t& r3, uint32_t addr) {
    asm volatile("ldmatrix.sync.aligned.m8n8.x4.trans.shared.b16 {%0,%1,%2,%3}, [%4];"
                 : "=r"(r0), "=r"(r1), "=r"(r2), "=r"(r3) : "r"(addr));
}
__device__ __forceinline__ void mma16816h(float* c, uint32_t a0, uint32_t a1,
                                          uint32_t a2, uint32_t a3,
                                          uint32_t b0, uint32_t b1) {
    asm volatile(
        "mma.sync.aligned.m16n8k16.row.col.f32.f16.f16.f32 "
        "{%0,%1,%2,%3},{%4,%5,%6,%7},{%8,%9},{%0,%1,%2,%3};"
        : "+f"(c[0]), "+f"(c[1]), "+f"(c[2]), "+f"(c[3])
        : "r"(a0), "r"(a1), "r"(a2), "r"(a3), "r"(b0), "r"(b1));
}
__device__ __forceinline__ uint32_t packf16(float hi, float lo) {
    uint32_t r;
    asm("cvt.rn.f16x2.f32 %0, %1, %2;" : "=r"(r) : "f"(hi), "f"(lo));
    return r;
}
__device__ __forceinline__ uint32_t exp2_f16x2(uint32_t x) {
    uint32_t r;
    asm("ex2.approx.f16x2 %0, %1;" : "=r"(r) : "r"(x));
    return r;
}

// ---------------------------------------------------------------------------
// fp16 single-product GEMM core: C[M,N] = Af[M,K] @ Bf[N,K]^T, fp32 accum.
// CTA 128x128, 128 threads (4 warps 2x2), warp tile 64x64, BK=64,
// 3-stage cp.async, 2 CTAs/SM, PERSISTENT tile loop.
// ---------------------------------------------------------------------------
#define GT       128
#define GKC      64
#define GK       2048
#define GNITER   (GK / GKC)               // 32
#define TILEB    16384                    // 128 rows x 128B
#define STAGEB   (2 * TILEB)              // Af, Bf
#define GSMEM3   (3 * STAGEB)             // 98304; 2 CTAs/SM -> 192KB
#define NPERS    296                      // 148 SMs x 2 CTAs

__device__ __forceinline__ void gemm_issue(
    uint32_t sb, int stage, int it,
    const __half* __restrict__ Af, const __half* __restrict__ Bf,
    int m0, int n0, int tid)
{
    const int k0 = it * GKC;
    const __half* srcs[2] = { Af, Bf };
#pragma unroll
    for (int mtx = 0; mtx < 2; mtx++) {
        const __half* src = srcs[mtx];
        const int rowbase = (mtx == 0) ? m0 : n0;
        const uint32_t smb = sb + stage * STAGEB + mtx * TILEB;
#pragma unroll
        for (int j = 0; j < 8; j++) {
            int chunk = tid + j * GT;          // 0..1023
            int row = chunk >> 3;
            int c16 = chunk & 7;
            const void* gp = src + (size_t)(rowbase + row) * GK + k0 + c16 * 8;
            uint32_t sp = smb + SWZ128(row * 128 + c16 * 16);
            asm volatile("cp.async.cg.shared.global [%0], [%1], 16;"
                         :: "r"(sp), "l"(gp));
        }
    }
    asm volatile("cp.async.commit_group;" ::: "memory");
}

__device__ __forceinline__ void gemm_mainloop(
    uint32_t sb, const __half* __restrict__ Af, const __half* __restrict__ Bf,
    int m0, int n0, int tid, float acc[4][8][4])
{
    const int wid = tid >> 5, l = tid & 31;
    const int wm = wid >> 1, wn = wid & 1;     // 2x2 warp grid
    const int a_row_l = (l & 7) + (l & 8);
    const int a_col_l = ((l >> 4) & 1) * 16;
    const int b_row_l = (l & 7) + ((l >> 4) & 1) * 8;
    const int b_col_l = ((l >> 3) & 1) * 16;

    gemm_issue(sb, 0, 0, Af, Bf, m0, n0, tid);
    gemm_issue(sb, 1, 1, Af, Bf, m0, n0, tid);

    for (int it = 0; it < GNITER; it++) {
        if (it + 1 < GNITER) {
            asm volatile("cp.async.wait_group 1;" ::: "memory");
        } else {
            asm volatile("cp.async.wait_group 0;" ::: "memory");
        }
        __syncthreads();
        if (it + 2 < GNITER)
            gemm_issue(sb, (it + 2) % 3, it + 2, Af, Bf, m0, n0, tid);

        const uint32_t stg = sb + (it % 3) * STAGEB;
        const uint32_t sAf = stg;
        const uint32_t sBf = stg + TILEB;

#pragma unroll
        for (int kk = 0; kk < 4; kk++) {
            const int kb = kk * 32;
            uint32_t af4[4][4], bf4[4][4];
#pragma unroll
            for (int mt = 0; mt < 4; mt++) {
                int row = wm * 64 + mt * 16 + a_row_l;
                uint32_t off = SWZ128(row * 128 + kb + a_col_l);
                ldsm4(af4[mt][0], af4[mt][1], af4[mt][2], af4[mt][3], sAf + off);
            }
#pragma unroll
            for (int nt2 = 0; nt2 < 4; nt2++) {
                int row = wn * 64 + nt2 * 16 + b_row_l;
                uint32_t off = SWZ128(row * 128 + kb + b_col_l);
                ldsm4(bf4[nt2][0], bf4[nt2][1], bf4[nt2][2], bf4[nt2][3], sBf + off);
            }
#pragma unroll
            for (int mt = 0; mt < 4; mt++)
#pragma unroll
                for (int nt = 0; nt < 8; nt++) {
                    uint32_t b0 = bf4[nt >> 1][(nt & 1) * 2];
                    uint32_t b1 = bf4[nt >> 1][(nt & 1) * 2 + 1];
                    mma16816h(acc[mt][nt], af4[mt][0], af4[mt][1],
                              af4[mt][2], af4[mt][3], b0, b1);
                }
        }
    }
}

// Fused QKV projection + RoPE, persistent tiles.
// n-tiles: [0,16): Q rope f16; [16,20): K rope f16; [20,24): V f16.
#define SROW 136   // fp32 staging row stride
#define QKV_NTN (NQKV / 128)    // 24
#define QKV_NT  ((MTOT / 128) * QKV_NTN)   // 1536
__global__ __launch_bounds__(GT, 2) void qkv_gemm_kernel(
    const __half* __restrict__ xf, const __half* __restrict__ wqkv)
{
    extern __shared__ char smem[];
    const uint32_t sb = smem_u32(smem);
    const int tid = threadIdx.x, wid = tid >> 5, l = tid & 31;
    const int wm = wid >> 1, wn = wid & 1;

    for (int tile = blockIdx.x; tile < QKV_NT; tile += gridDim.x) {
        const int m0 = (tile / QKV_NTN) * 128;
        const int n0 = (tile % QKV_NTN) * 128;

        float acc[4][8][4];
#pragma unroll
        for (int i = 0; i < 4; i++)
#pragma unroll
            for (int j = 0; j < 8; j++)
#pragma unroll
                for (int f = 0; f < 4; f++) acc[i][j][f] = 0.f;

        gemm_mainloop(sb, xf, wqkv, m0, n0, tid, acc);

        if (n0 >= DMODEL + NKVD) {
            // V: direct f16 store
            int nb = n0 - DMODEL - NKVD;
#pragma unroll
            for (int mt = 0; mt < 4; mt++) {
                int r0 = m0 + wm * 64 + mt * 16 + (l >> 2);
#pragma unroll
                for (int nt = 0; nt < 8; nt++) {
                    int c = nb + wn * 64 + nt * 8 + (l & 3) * 2;
                    *(__half2*)(g_vf + (size_t)r0 * NKVD + c) =
                        __floats2half2_rn(acc[mt][nt][0], acc[mt][nt][1]);
                    *(__half2*)(g_vf + (size_t)(r0 + 8) * NKVD + c) =
                        __floats2half2_rn(acc[mt][nt][2], acc[mt][nt][3]);
                }
            }
            __syncthreads();   // smem reuse fence before next tile's issues
            continue;
        }

        // Q or K: stage fp32 tile in smem, apply RoPE, convert, store
        float* sst = (float*)smem;
        __syncthreads();   // mainloop smem no longer needed
#pragma unroll
        for (int mt = 0; mt < 4; mt++) {
            int r0 = wm * 64 + mt * 16 + (l >> 2);
#pragma unroll
            for (int nt = 0; nt < 8; nt++) {
                int c = wn * 64 + nt * 8 + (l & 3) * 2;
                *(float2*)&sst[r0 * SROW + c] = make_float2(acc[mt][nt][0], acc[mt][nt][1]);
                *(float2*)&sst[(r0 + 8) * SROW + c] = make_float2(acc[mt][nt][2], acc[mt][nt][3]);
            }
        }
        __syncthreads();

        const bool isQ = (n0 < DMODEL);
#pragma unroll
        for (int j = 0; j < 8; j++) {
            int idx = tid + j * GT;
            int rl = idx >> 3;
            int c8 = (idx & 7) * 8;
            int grow = m0 + rl;
            int s = grow & (SEQ - 1);
            float x1[8], x2[8];
            *(float4*)(x1)     = *(float4*)&sst[rl * SROW + c8];
            *(float4*)(x1 + 4) = *(float4*)&sst[rl * SROW + c8 + 4];
            *(float4*)(x2)     = *(float4*)&sst[rl * SROW + c8 + 64];
            *(float4*)(x2 + 4) = *(float4*)&sst[rl * SROW + c8 + 68];
            const float* tc = g_ropec + s * 64 + c8;
            const float* ts = g_ropes + s * 64 + c8;
            __half h1[8], h2[8];
#pragma unroll
            for (int u = 0; u < 8; u++) {
                float c = tc[u], sn = ts[u];
                h1[u] = __float2half(x1[u] * c - x2[u] * sn);
                h2[u] = __float2half(x2[u] * c + x1[u] * sn);
            }
            if (isQ) {
                size_t base = (size_t)grow * DMODEL + n0 + c8;
                *(uint4*)(g_qf + base)      = *(uint4*)h1;
                *(uint4*)(g_qf + base + 64) = *(uint4*)h2;
            } else {
                size_t base = (size_t)grow * NKVD + (n0 - DMODEL) + c8;
                *(uint4*)(g_kf + base)      = *(uint4*)h1;
                *(uint4*)(g_kf + base + 64) = *(uint4*)h2;
            }
        }
        __syncthreads();   // sst reads done before next tile overwrites smem
    }
}

// Output projection, persistent tiles: N = 2048, fp32 out
#define OP_NTN (DMODEL / 128)   // 16
#define OP_NT  ((MTOT / 128) * OP_NTN)   // 1024
__global__ __launch_bounds__(GT, 2) void oproj_gemm_kernel(
    const __half* __restrict__ Af, const __half* __restrict__ Bf,
    float* __restrict__ C)
{
    extern __shared__ char smem[];
    const uint32_t sb = smem_u32(smem);
    const int tid = threadIdx.x, wid = tid >> 5, l = tid & 31;
    const int wm = wid >> 1, wn = wid & 1;

    for (int tile = blockIdx.x; tile < OP_NT; tile += gridDim.x) {
        const int m0 = (tile / OP_NTN) * 128;
        const int n0 = (tile % OP_NTN) * 128;

        float acc[4][8][4];
#pragma unroll
        for (int i = 0; i < 4; i++)
#pragma unroll
            for (int j = 0; j < 8; j++)
#pragma unroll
                for (int f = 0; f < 4; f++) acc[i][j][f] = 0.f;

        gemm_mainloop(sb, Af, Bf, m0, n0, tid, acc);

#pragma unroll
        for (int mt = 0; mt < 4; mt++) {
            int r0 = m0 + wm * 64 + mt * 16 + (l >> 2);
#pragma unroll
            for (int nt = 0; nt < 8; nt++) {
                int c = n0 + wn * 64 + nt * 8 + (l & 3) * 2;
                *(float2*)(C + (size_t)r0 * DMODEL + c) =
                    make_float2(acc[mt][nt][0], acc[mt][nt][1]);
                *(float2*)(C + (size_t)(r0 + 8) * DMODEL + c) =
                    make_float2(acc[mt][nt][2], acc[mt][nt][3]);
            }
        }
        __syncthreads();   // smem reuse fence before next tile's issues
    }
}

// ---------------------------------------------------------------------------
// elementwise converters
// ---------------------------------------------------------------------------
__global__ void f16conv_kernel(const float4* __restrict__ in,
                               __half2* __restrict__ out, int n4)
{
    int i = blockIdx.x * blockDim.x + threadIdx.x;
    if (i >= n4) return;
    float4 v = in[i];
    out[2 * i]     = __floats2half2_rn(v.x, v.y);
    out[2 * i + 1] = __floats2half2_rn(v.z, v.w);
}

// fused weight transpose: all four weights in one launch (z selects)
__global__ void wconv_kernel(const float* __restrict__ wq,
                             const float* __restrict__ wk,
                             const float* __restrict__ wv,
                             const float* __restrict__ wo,
                             __half* __restrict__ wqkv,
                             __half* __restrict__ wof)
{
    __shared__ float tile[32][33];
    const int z = blockIdx.z;
    const float* w;
    __half* tf;
    int Nd;
    if (z == 0)      { w = wq; tf = wqkv;                                    Nd = DMODEL; }
    else if (z == 1) { w = wk; tf = wqkv + (size_t)DMODEL * DMODEL;          Nd = NKVD; }
    else if (z == 2) { w = wv; tf = wqkv + (size_t)(DMODEL + NKVD) * DMODEL; Nd = NKVD; }
    else             { w = wo; tf = wof;                                     Nd = DMODEL; }

    int n0 = blockIdx.x * 32, k0 = blockIdx.y * 32;
    if (n0 >= Nd) return;
    int tx = threadIdx.x, ty = threadIdx.y;
#pragma unroll
    for (int j = 0; j < 32; j += 8)
        tile[ty + j][tx] = w[(size_t)(k0 + ty + j) * Nd + n0 + tx];
    __syncthreads();
#pragma unroll
    for (int j = 0; j < 32; j += 8) {
        float x = tile[tx][ty + j];
        tf[(size_t)(n0 + ty + j) * DMODEL + k0 + tx] = __float2half(x);
    }
}

// RoPE table precompute (fp64 trig)
__global__ void rope_table_kernel()
{
    int idx = blockIdx.x * blockDim.x + threadIdx.x;
    if (idx >= SEQ * 64) return;
    int i = idx & 63, s = idx >> 6;
    double inv = exp(-0.14391156831212787 * (double)i);
    double sd, cd;
    sincos((double)s * inv, &sd, &cd);
    g_ropec[idx] = (float)cd;
    g_ropes[idx] = (float)sd;
}

// ---------------------------------------------------------------------------
// HMMA flash attention: Q, K, V all single f16 (1-product QK). (unchanged)
// ---------------------------------------------------------------------------
#define AT_STAGE0 32768
#define AT_STAGEB 32768
#define AT_SMEM   (AT_STAGE0 + 3 * AT_STAGEB)   // 131072

__device__ __forceinline__ void attn_issue_kv(
    uint32_t stbase, const __half* kfg, const __half* vg, int k0, int tid)
{
    const char* bases[2] = { (const char*)kfg, (const char*)vg };
#pragma unroll
    for (int arr = 0; arr < 2; arr++) {
        const char* base = bases[arr];
        uint32_t soff = stbase + arr * 16384;
#pragma unroll
        for (int i = 0; i < 4; i++) {
            int chunk = tid + i * 256;
            int row = chunk >> 4, cc = chunk & 15;
            const void* gp = base + ((size_t)(k0 + row) * NKVD + cc * 8) * 2;
            uint32_t sp = soff + (cc >> 3) * 8192 + SWZ128(row * 128 + (cc & 7) * 16);
            asm volatile("cp.async.cg.shared.global [%0], [%1], 16;"
                         :: "r"(sp), "l"(gp));
        }
    }
    asm volatile("cp.async.commit_group;" ::: "memory");
}

__global__ __launch_bounds__(256, 1) void hmma_attn_kernel(const float* __restrict__ tptr)
{
    extern __shared__ char smem[];
    const uint32_t sb = smem_u32(smem);
    const int tid = threadIdx.x, w = tid >> 5, l = tid & 31;
    const int qt = gridDim.x - 1 - blockIdx.x;   // LPT: heaviest first
    const int h = blockIdx.y, b = blockIdx.z;
    const int kv = h >> 2;
    const int q0 = qt * 128;
    const int qw0 = q0 + w * 16;
    const float scale = 0.08838834764831845f / fmaxf(fabsf(tptr[0]), 1e-6f);
    const float sl = scale * 1.4426950408889634f;

    const uint32_t sQ = sb;

    const __half* qfg = g_qf + ((size_t)(b * SEQ) + q0) * DMODEL + h * DHEAD;
    const __half* kfg = g_kf + (size_t)(b * SEQ) * NKVD + kv * DHEAD;
    const __half* vg  = g_vf + (size_t)(b * SEQ) * NKVD + kv * DHEAD;

    const int nkt = 2 * qt + 2;

    // prologue
    {
#pragma unroll
        for (int i = 0; i < 8; i++) {
            int chunk = tid + i * 256;
            int row = chunk >> 4, cc = chunk & 15;
            const void* gp = (const char*)qfg + ((size_t)row * DMODEL + cc * 8) * 2;
            uint32_t sp = sQ + (cc >> 3) * 16384 + SWZ128(row * 128 + (cc & 7) * 16);
            asm volatile("cp.async.cg.shared.global [%0], [%1], 16;"
                         :: "r"(sp), "l"(gp));
        }
        attn_issue_kv(sb + AT_STAGE0, kfg, vg, 0, tid);
        attn_issue_kv(sb + AT_STAGE0 + AT_STAGEB, kfg, vg, 64, tid);
    }

    const int a_row_l = (l & 7) + (l & 8);
    const int a_col_l = ((l >> 4) & 1) * 16;
    const int b_row_l = (l & 7) + ((l >> 4) & 1) * 8;
    const int b_col_l = ((l >> 3) & 1) * 16;
    const int v_row_l = (l & 7) + ((l >> 3) & 1) * 8;
    const int v_col_l = ((l >> 4) & 1) * 16;

    float oacc[16][4];
    float lacc[4] = {0.f, 0.f, 0.f, 0.f};
#pragma unroll
    for (int i = 0; i < 16; i++)
#pragma unroll
        for (int f = 0; f < 4; f++) oacc[i][f] = 0.f;
    float m0 = -3.0e38f, m1 = -3.0e38f;

    for (int kt = 0; kt < nkt; kt++) {
        if (kt + 1 < nkt) {
            asm volatile("cp.async.wait_group 1;" ::: "memory");
        } else {
            asm volatile("cp.async.wait_group 0;" ::: "memory");
        }
        __syncthreads();
        if (kt + 2 < nkt)
            attn_issue_kv(sb + AT_STAGE0 + ((kt + 2) % 3) * AT_STAGEB,
                          kfg, vg, (kt + 2) * 64, tid);

        const int k0 = kt * 64;
        const uint32_t st = sb + AT_STAGE0 + (kt % 3) * AT_STAGEB;

        if (k0 <= qw0 + 15) {
            float sacc[8][4];
#pragma unroll
            for (int i = 0; i < 8; i++)
#pragma unroll
                for (int f = 0; f < 4; f++) sacc[i][f] = 0.f;

#pragma unroll
            for (int ks = 0; ks < 8; ks++) {
                uint32_t qoff = (ks >> 2) * 16384 +
                    SWZ128((w * 16 + a_row_l) * 128 + (ks & 3) * 32 + a_col_l);
                uint32_t qa[4];
                ldsm4(qa[0], qa[1], qa[2], qa[3], sQ + qoff);
#pragma unroll
                for (int np = 0; np < 4; np++) {
                    uint32_t koff = st + (ks >> 2) * 8192 +
                        SWZ128((np * 16 + b_row_l) * 128 + (ks & 3) * 32 + b_col_l);
                    uint32_t kf4[4];
                    ldsm4(kf4[0], kf4[1], kf4[2], kf4[3], koff);
                    mma16816h(sacc[2 * np],     qa[0], qa[1], qa[2], qa[3], kf4[0], kf4[1]);
                    mma16816h(sacc[2 * np + 1], qa[0], qa[1], qa[2], qa[3], kf4[2], kf4[3]);
                }
            }

            if (k0 + 63 > qw0) {
                int qa0 = qw0 + (l >> 2), qa1 = qa0 + 8;
                int kc0 = k0 + 2 * (l & 3);
#pragma unroll
                for (int nt = 0; nt < 8; nt++) {
                    int kc = kc0 + nt * 8;
                    if (kc     > qa0) sacc[nt][0] = -3.0e38f;
                    if (kc + 1 > qa0) sacc[nt][1] = -3.0e38f;
                    if (kc     > qa1) sacc[nt][2] = -3.0e38f;
                    if (kc + 1 > qa1) sacc[nt][3] = -3.0e38f;
                }
            }

            float mx0 = -3.0e38f, mx1 = -3.0e38f;
#pragma unroll
            for (int nt = 0; nt < 8; nt++) {
                mx0 = fmaxf(mx0, fmaxf(sacc[nt][0], sacc[nt][1]));
                mx1 = fmaxf(mx1, fmaxf(sacc[nt][2], sacc[nt][3]));
            }
            mx0 = fmaxf(mx0, __shfl_xor_sync(0xffffffffu, mx0, 1));
            mx0 = fmaxf(mx0, __shfl_xor_sync(0xffffffffu, mx0, 2));
            mx1 = fmaxf(mx1, __shfl_xor_sync(0xffffffffu, mx1, 1));
            mx1 = fmaxf(mx1, __shfl_xor_sync(0xffffffffu, mx1, 2));
            float mn0 = fmaxf(m0, mx0), mn1 = fmaxf(m1, mx1);
            bool ch = (mn0 > m0) || (mn1 > m1);
            if (__any_sync(0xffffffffu, ch)) {
                float a0 = exp2f((m0 - mn0) * sl);
                float a1 = exp2f((m1 - mn1) * sl);
#pragma unroll
                for (int nt = 0; nt < 16; nt++) {
                    oacc[nt][0] *= a0; oacc[nt][1] *= a0;
                    oacc[nt][2] *= a1; oacc[nt][3] *= a1;
                }
                lacc[0] *= a0; lacc[1] *= a0; lacc[2] *= a1; lacc[3] *= a1;
            }
            m0 = mn0; m1 = mn1;
            const float bb0 = mn0 * sl, bb1 = mn1 * sl;

            uint32_t pp[8][2];
#pragma unroll
            for (int nt = 0; nt < 8; nt++) {
                float t0 = fmaf(sacc[nt][0], sl, -bb0);
                float t1 = fmaf(sacc[nt][1], sl, -bb0);
                float t2 = fmaf(sacc[nt][2], sl, -bb1);
                float t3 = fmaf(sacc[nt][3], sl, -bb1);
                pp[nt][0] = exp2_f16x2(packf16(t1, t0));
                pp[nt][1] = exp2_f16x2(packf16(t3, t2));
            }

#pragma unroll
            for (int ks = 0; ks < 4; ks++) {
                uint32_t pa0 = pp[2 * ks][0], pa1 = pp[2 * ks][1];
                uint32_t pa2 = pp[2 * ks + 1][0], pa3 = pp[2 * ks + 1][1];
                mma16816h(lacc, pa0, pa1, pa2, pa3, 0x3C003C00u, 0x3C003C00u);
#pragma unroll
                for (int jp = 0; jp < 8; jp++) {
                    uint32_t voff = st + 16384 + (jp >> 2) * 8192 +
                        SWZ128((ks * 16 + v_row_l) * 128 + (jp & 3) * 32 + v_col_l);
                    uint32_t v4[4];
                    ldsm4t(v4[0], v4[1], v4[2], v4[3], voff);
                    mma16816h(oacc[2 * jp],     pa0, pa1, pa2, pa3, v4[0], v4[1]);
                    mma16816h(oacc[2 * jp + 1], pa0, pa1, pa2, pa3, v4[2], v4[3]);
                }
            }
        }
    }

    // epilogue: normalize + single f16 store
    const float inv0 = 1.0f / lacc[0];
    const float inv1 = 1.0f / lacc[2];
    const size_t r0g = (size_t)(b * SEQ) + qw0 + (l >> 2);
    const size_t r1g = r0g + 8;
#pragma unroll
    for (int nt = 0; nt < 16; nt++) {
        int col = h * DHEAD + nt * 8 + 2 * (l & 3);
        *(__half2*)(g_of + r0g * DMODEL + col) =
            __floats2half2_rn(oacc[nt][0] * inv0, oacc[nt][1] * inv0);
        *(__half2*)(g_of + r1g * DMODEL + col) =
            __floats2half2_rn(oacc[nt][2] * inv1, oacc[nt][3] * inv1);
    }
}

// ---------------------------------------------------------------------------
extern "C" void kernel_launch(void* const* d_in, const int* in_sizes, int n_in,
                              void* d_out, int out_size)
{
    const float* x  = (const float*)d_in[0];
    const float* wq = (const float*)d_in[1];
    const float* wk = (const float*)d_in[2];
    const float* wv = (const float*)d_in[3];
    const float* wo = (const float*)d_in[4];
    const float* tp = (const float*)d_in[5];
    float* out = (float*)d_out;

    __half *xf, *of, *wqkv, *wof;
    cudaGetSymbolAddress((void**)&xf, g_xf);
    cudaGetSymbolAddress((void**)&of, g_of);
    cudaGetSymbolAddress((void**)&wqkv, g_wqkv);
    cudaGetSymbolAddress((void**)&wof, g_wof);

    cudaFuncSetAttribute(qkv_gemm_kernel, cudaFuncAttributeMaxDynamicSharedMemorySize, GSMEM3);
    cudaFuncSetAttribute(oproj_gemm_kernel, cudaFuncAttributeMaxDynamicSharedMemorySize, GSMEM3);
    cudaFuncSetAttribute(hmma_attn_kernel, cudaFuncAttributeMaxDynamicSharedMemorySize, AT_SMEM);

    // converters + rope table
    rope_table_kernel<<<(SEQ * 64 + 255) / 256, 256>>>();
    {
        int n4 = MTOT * DMODEL / 4;
        f16conv_kernel<<<(n4 + 255) / 256, 256>>>((const float4*)x, (__half2*)xf, n4);
        wconv_kernel<<<dim3(DMODEL / 32, DMODEL / 32, 4), dim3(32, 8)>>>(
            wq, wk, wv, wo, wqkv, wof);
    }

    // fused QKV projection + RoPE (persistent, 2 CTAs/SM)
    qkv_gemm_kernel<<<NPERS, GT, GSMEM3>>>(xf, wqkv);

    // flash attention (single-product QK)
    hmma_attn_kernel<<<dim3(SEQ / 128, NHEADS, BATCH), 256, AT_SMEM>>>(tp);

    // output projection (persistent, 2 CTAs/SM)
    oproj_gemm_kernel<<<NPERS, GT, GSMEM3>>>(of, wof, out);
}

// round 14
// speedup vs baseline: 1.0893x; 1.0893x over previous
#include <cuda_runtime.h>
#include <cuda_bf16.h>
#include <cuda_fp16.h>
#include <math.h>
#include <stdint.h>

#define BATCH   4
#define SEQ     2048
#define DMODEL  2048
#define NHEADS  16
#define NKV     4
#define DHEAD   128
#define MTOT    (BATCH * SEQ)          // 8192
#define NKVD    (NKV * DHEAD)          // 512
#define NQKV    (DMODEL + 2 * NKVD)    // 3072

// ---------------- scratch ----------
__device__ __half g_qf[MTOT * DMODEL];                       // roped Q f16
__device__ __half g_kf[MTOT * NKVD];                         // roped K f16
__device__ __half g_vf[MTOT * NKVD];                         // V f16

__device__ __half g_xf[MTOT * DMODEL];                       // x f16
__device__ __half g_of[MTOT * DMODEL];                       // attn out f16
__device__ __half g_wqkv[NQKV * DMODEL];                     // [Wq;Wk;Wv]^T f16
__device__ __half g_wof[DMODEL * DMODEL];

__device__ float g_ropec[SEQ * 64], g_ropes[SEQ * 64];

// ---------------- helpers ---------------------------------------------
__device__ __forceinline__ uint32_t smem_u32(const void* p) {
    uint32_t a;
    asm("{ .reg .u64 t; cvta.to.shared.u64 t, %1; cvt.u32.u64 %0, t; }"
        : "=r"(a) : "l"(p));
    return a;
}
#define SWZ128(o) ((o) ^ (((o) >> 3) & 0x70))

__device__ __forceinline__ void ldsm4(uint32_t& r0, uint32_t& r1,
                                      uint32_t& r2, uint32_t& r3, uint32_t addr) {
    asm volatile("ldmatrix.sync.aligned.m8n8.x4.shared.b16 {%0,%1,%2,%3}, [%4];"
                 : "=r"(r0), "=r"(r1), "=r"(r2), "=r"(r3) : "r"(addr));
}
__device__ __forceinline__ void ldsm4t(uint32_t& r0, uint32_t& r1,
                                       uint32_t& r2, uint32_t& r3, uint32_t addr) {
    asm volatile("ldmatrix.sync.aligned.m8n8.x4.trans.shared.b16 {%0,%1,%2,%3}, [%4];"
                 : "=r"(r0), "=r"(r1), "=r"(r2), "=r"(r3) : "r"(addr));
}
__device__ __forceinline__ void mma16816h(float* c, uint32_t a0, uint32_t a1,
                                          uint32_t a2, uint32_t a3,
                                          uint32_t b0, uint32_t b1) {
    asm volatile(
        "mma.sync.aligned.m16n8k16.row.col.f32.f16.f16.f32 "
        "{%0,%1,%2,%3},{%4,%5,%6,%7},{%8,%9},{%0,%1,%2,%3};"
        : "+f"(c[0]), "+f"(c[1]), "+f"(c[2]), "+f"(c[3])
        : "r"(a0), "r"(a1), "r"(a2), "r"(a3), "r"(b0), "r"(b1));
}
__device__ __forceinline__ uint32_t packf16(float hi, float lo) {
    uint32_t r;
    asm("cvt.rn.f16x2.f32 %0, %1, %2;" : "=r"(r) : "f"(hi), "f"(lo));
    return r;
}
__device__ __forceinline__ uint32_t exp2_f16x2(uint32_t x) {
    uint32_t r;
    asm("ex2.approx.f16x2 %0, %1;" : "=r"(r) : "r"(x));
    return r;
}

// ---------------------------------------------------------------------------
// fp16 single-product GEMM core (round-12 form): C[M,N] = Af[M,K] @ Bf[N,K]^T
// CTA 128x128, 128 threads (4 warps 2x2), warp tile 64x64, BK=64,
// 3-stage cp.async, 2 CTAs/SM.
// ---------------------------------------------------------------------------
#define GT       128
#define GKC      64
#define GK       2048
#define GNITER   (GK / GKC)               // 32
#define TILEB    16384                    // 128 rows x 128B
#define STAGEB   (2 * TILEB)              // Af, Bf
#define GSMEM3   (3 * STAGEB)             // 98304; 2 CTAs/SM -> 192KB

__device__ __forceinline__ void gemm_issue(
    uint32_t sb, int stage, int it,
    const __half* __restrict__ Af, const __half* __restrict__ Bf,
    int m0, int n0, int tid)
{
    const int k0 = it * GKC;
    const __half* srcs[2] = { Af, Bf };
#pragma unroll
    for (int mtx = 0; mtx < 2; mtx++) {
        const __half* src = srcs[mtx];
        const int rowbase = (mtx == 0) ? m0 : n0;
        const uint32_t smb = sb + stage * STAGEB + mtx * TILEB;
#pragma unroll
        for (int j = 0; j < 8; j++) {
            int chunk = tid + j * GT;          // 0..1023
            int row = chunk >> 3;
            int c16 = chunk & 7;
            const void* gp = src + (size_t)(rowbase + row) * GK + k0 + c16 * 8;
            uint32_t sp = smb + SWZ128(row * 128 + c16 * 16);
            asm volatile("cp.async.cg.shared.global [%0], [%1], 16;"
                         :: "r"(sp), "l"(gp));
        }
    }
    asm volatile("cp.async.commit_group;" ::: "memory");
}

__device__ __forceinline__ void gemm_mainloop(
    uint32_t sb, const __half* __restrict__ Af, const __half* __restrict__ Bf,
    int m0, int n0, int tid, float acc[4][8][4])
{
    const int wid = tid >> 5, l = tid & 31;
    const int wm = wid >> 1, wn = wid & 1;     // 2x2 warp grid
    const int a_row_l = (l & 7) + (l & 8);
    const int a_col_l = ((l >> 4) & 1) * 16;
    const int b_row_l = (l & 7) + ((l >> 4) & 1) * 8;
    const int b_col_l = ((l >> 3) & 1) * 16;

    gemm_issue(sb, 0, 0, Af, Bf, m0, n0, tid);
    gemm_issue(sb, 1, 1, Af, Bf, m0, n0, tid);

    for (int it = 0; it < GNITER; it++) {
        if (it + 1 < GNITER) {
            asm volatile("cp.async.wait_group 1;" ::: "memory");
        } else {
            asm volatile("cp.async.wait_group 0;" ::: "memory");
        }
        __syncthreads();
        if (it + 2 < GNITER)
            gemm_issue(sb, (it + 2) % 3, it + 2, Af, Bf, m0, n0, tid);

        const uint32_t stg = sb + (it % 3) * STAGEB;
        const uint32_t sAf = stg;
        const uint32_t sBf = stg + TILEB;

#pragma unroll
        for (int kk = 0; kk < 4; kk++) {
            const int kb = kk * 32;
            uint32_t af4[4][4], bf4[4][4];
#pragma unroll
            for (int mt = 0; mt < 4; mt++) {
                int row = wm * 64 + mt * 16 + a_row_l;
                uint32_t off = SWZ128(row * 128 + kb + a_col_l);
                ldsm4(af4[mt][0], af4[mt][1], af4[mt][2], af4[mt][3], sAf + off);
            }
#pragma unroll
            for (int nt2 = 0; nt2 < 4; nt2++) {
                int row = wn * 64 + nt2 * 16 + b_row_l;
                uint32_t off = SWZ128(row * 128 + kb + b_col_l);
                ldsm4(bf4[nt2][0], bf4[nt2][1], bf4[nt2][2], bf4[nt2][3], sBf + off);
            }
#pragma unroll
            for (int mt = 0; mt < 4; mt++)
#pragma unroll
                for (int nt = 0; nt < 8; nt++) {
                    uint32_t b0 = bf4[nt >> 1][(nt & 1) * 2];
                    uint32_t b1 = bf4[nt >> 1][(nt & 1) * 2 + 1];
                    mma16816h(acc[mt][nt], af4[mt][0], af4[mt][1],
                              af4[mt][2], af4[mt][3], b0, b1);
                }
        }
    }
}

// Fused QKV projection + RoPE.
#define SROW 136   // fp32 staging row stride
__global__ __launch_bounds__(GT, 2) void qkv_gemm_kernel(
    const __half* __restrict__ xf, const __half* __restrict__ wqkv)
{
    extern __shared__ char smem[];
    const uint32_t sb = smem_u32(smem);
    const int tid = threadIdx.x, wid = tid >> 5, l = tid & 31;
    const int wm = wid >> 1, wn = wid & 1;
    const int m0 = blockIdx.y * 128;
    const int n0 = blockIdx.x * 128;

    float acc[4][8][4];
#pragma unroll
    for (int i = 0; i < 4; i++)
#pragma unroll
        for (int j = 0; j < 8; j++)
#pragma unroll
            for (int f = 0; f < 4; f++) acc[i][j][f] = 0.f;

    gemm_mainloop(sb, xf, wqkv, m0, n0, tid, acc);

    if (n0 >= DMODEL + NKVD) {
        int nb = n0 - DMODEL - NKVD;
#pragma unroll
        for (int mt = 0; mt < 4; mt++) {
            int r0 = m0 + wm * 64 + mt * 16 + (l >> 2);
#pragma unroll
            for (int nt = 0; nt < 8; nt++) {
                int c = nb + wn * 64 + nt * 8 + (l & 3) * 2;
                *(__half2*)(g_vf + (size_t)r0 * NKVD + c) =
                    __floats2half2_rn(acc[mt][nt][0], acc[mt][nt][1]);
                *(__half2*)(g_vf + (size_t)(r0 + 8) * NKVD + c) =
                    __floats2half2_rn(acc[mt][nt][2], acc[mt][nt][3]);
            }
        }
        return;
    }

    float* sst = (float*)smem;
    __syncthreads();
#pragma unroll
    for (int mt = 0; mt < 4; mt++) {
        int r0 = wm * 64 + mt * 16 + (l >> 2);
#pragma unroll
        for (int nt = 0; nt < 8; nt++) {
            int c = wn * 64 + nt * 8 + (l & 3) * 2;
            *(float2*)&sst[r0 * SROW + c] = make_float2(acc[mt][nt][0], acc[mt][nt][1]);
            *(float2*)&sst[(r0 + 8) * SROW + c] = make_float2(acc[mt][nt][2], acc[mt][nt][3]);
        }
    }
    __syncthreads();

    const bool isQ = (n0 < DMODEL);
#pragma unroll
    for (int j = 0; j < 8; j++) {
        int idx = tid + j * GT;
        int rl = idx >> 3;
        int c8 = (idx & 7) * 8;
        int grow = m0 + rl;
        int s = grow & (SEQ - 1);
        float x1[8], x2[8];
        *(float4*)(x1)     = *(float4*)&sst[rl * SROW + c8];
        *(float4*)(x1 + 4) = *(float4*)&sst[rl * SROW + c8 + 4];
        *(float4*)(x2)     = *(float4*)&sst[rl * SROW + c8 + 64];
        *(float4*)(x2 + 4) = *(float4*)&sst[rl * SROW + c8 + 68];
        const float* tc = g_ropec + s * 64 + c8;
        const float* ts = g_ropes + s * 64 + c8;
        __half h1[8], h2[8];
#pragma unroll
        for (int u = 0; u < 8; u++) {
            float c = tc[u], sn = ts[u];
            h1[u] = __float2half(x1[u] * c - x2[u] * sn);
            h2[u] = __float2half(x2[u] * c + x1[u] * sn);
        }
        if (isQ) {
            size_t base = (size_t)grow * DMODEL + n0 + c8;
            *(uint4*)(g_qf + base)      = *(uint4*)h1;
            *(uint4*)(g_qf + base + 64) = *(uint4*)h2;
        } else {
            size_t base = (size_t)grow * NKVD + (n0 - DMODEL) + c8;
            *(uint4*)(g_kf + base)      = *(uint4*)h1;
            *(uint4*)(g_kf + base + 64) = *(uint4*)h2;
        }
    }
}

// Output projection
__global__ __launch_bounds__(GT, 2) void oproj_gemm_kernel(
    const __half* __restrict__ Af, const __half* __restrict__ Bf,
    float* __restrict__ C)
{
    extern __shared__ char smem[];
    const uint32_t sb = smem_u32(smem);
    const int tid = threadIdx.x, wid = tid >> 5, l = tid & 31;
    const int wm = wid >> 1, wn = wid & 1;
    const int m0 = blockIdx.y * 128;
    const int n0 = blockIdx.x * 128;

    float acc[4][8][4];
#pragma unroll
    for (int i = 0; i < 4; i++)
#pragma unroll
        for (int j = 0; j < 8; j++)
#pragma unroll
            for (int f = 0; f < 4; f++) acc[i][j][f] = 0.f;

    gemm_mainloop(sb, Af, Bf, m0, n0, tid, acc);

#pragma unroll
    for (int mt = 0; mt < 4; mt++) {
        int r0 = m0 + wm * 64 + mt * 16 + (l >> 2);
#pragma unroll
        for (int nt = 0; nt < 8; nt++) {
            int c = n0 + wn * 64 + nt * 8 + (l & 3) * 2;
            *(float2*)(C + (size_t)r0 * DMODEL + c) =
                make_float2(acc[mt][nt][0], acc[mt][nt][1]);
            *(float2*)(C + (size_t)(r0 + 8) * DMODEL + c) =
                make_float2(acc[mt][nt][2], acc[mt][nt][3]);
        }
    }
}

// ---------------------------------------------------------------------------
// elementwise converters
// ---------------------------------------------------------------------------
__global__ void f16conv_kernel(const float4* __restrict__ in,
                               __half2* __restrict__ out, int n4)
{
    int i = blockIdx.x * blockDim.x + threadIdx.x;
    if (i >= n4) return;
    float4 v = in[i];
    out[2 * i]     = __floats2half2_rn(v.x, v.y);
    out[2 * i + 1] = __floats2half2_rn(v.z, v.w);
}

// fused weight transpose: all four weights in one launch (z selects)
__global__ void wconv_kernel(const float* __restrict__ wq,
                             const float* __restrict__ wk,
                             const float* __restrict__ wv,
                             const float* __restrict__ wo,
                             __half* __restrict__ wqkv,
                             __half* __restrict__ wof)
{
    __shared__ float tile[32][33];
    const int z = blockIdx.z;
    const float* w;
    __half* tf;
    int Nd;
    if (z == 0)      { w = wq; tf = wqkv;                                    Nd = DMODEL; }
    else if (z == 1) { w = wk; tf = wqkv + (size_t)DMODEL * DMODEL;          Nd = NKVD; }
    else if (z == 2) { w = wv; tf = wqkv + (size_t)(DMODEL + NKVD) * DMODEL; Nd = NKVD; }
    else             { w = wo; tf = wof;                                     Nd = DMODEL; }

    int n0 = blockIdx.x * 32, k0 = blockIdx.y * 32;
    if (n0 >= Nd) return;
    int tx = threadIdx.x, ty = threadIdx.y;
#pragma unroll
    for (int j = 0; j < 32; j += 8)
        tile[ty + j][tx] = w[(size_t)(k0 + ty + j) * Nd + n0 + tx];
    __syncthreads();
#pragma unroll
    for (int j = 0; j < 32; j += 8) {
        float x = tile[tx][ty + j];
        tf[(size_t)(n0 + ty + j) * DMODEL + k0 + tx] = __float2half(x);
    }
}

// RoPE table precompute (fp64 trig)
__global__ void rope_table_kernel()
{
    int idx = blockIdx.x * blockDim.x + threadIdx.x;
    if (idx >= SEQ * 64) return;
    int i = idx & 63, s = idx >> 6;
    double inv = exp(-0.14391156831212787 * (double)i);
    double sd, cd;
    sincos((double)s * inv, &sd, &cd);
    g_ropec[idx] = (float)cd;
    g_ropes[idx] = (float)sd;
}

// ---------------------------------------------------------------------------
// HMMA flash attention: CTA = 64 q-rows, 128 threads (4 warps), 2 CTAs/SM.
// Q/K/V single f16; 3-stage KV pipeline; per-warp math identical to round 9.
// smem: Q 16KB + 3 x 32KB KV = 112KB.
// ---------------------------------------------------------------------------
#define AT_T     128
#define AT_STAGE0 16384
#define AT_STAGEB 32768
#define AT_SMEM   (AT_STAGE0 + 3 * AT_STAGEB)   // 114688; 2 CTAs = 229376

__device__ __forceinline__ void attn_issue_kv(
    uint32_t stbase, const __half* kfg, const __half* vg, int k0, int tid)
{
    const char* bases[2] = { (const char*)kfg, (const char*)vg };
#pragma unroll
    for (int arr = 0; arr < 2; arr++) {
        const char* base = bases[arr];
        uint32_t soff = stbase + arr * 16384;
#pragma unroll
        for (int i = 0; i < 8; i++) {
            int chunk = tid + i * AT_T;
            int row = chunk >> 4, cc = chunk & 15;
            const void* gp = base + ((size_t)(k0 + row) * NKVD + cc * 8) * 2;
            uint32_t sp = soff + (cc >> 3) * 8192 + SWZ128(row * 128 + (cc & 7) * 16);
            asm volatile("cp.async.cg.shared.global [%0], [%1], 16;"
                         :: "r"(sp), "l"(gp));
        }
    }
    asm volatile("cp.async.commit_group;" ::: "memory");
}

__global__ __launch_bounds__(AT_T, 2) void hmma_attn_kernel(const float* __restrict__ tptr)
{
    extern __shared__ char smem[];
    const uint32_t sb = smem_u32(smem);
    const int tid = threadIdx.x, w = tid >> 5, l = tid & 31;
    const int qt = gridDim.x - 1 - blockIdx.x;   // LPT: heaviest first
    const int h = blockIdx.y, b = blockIdx.z;
    const int kv = h >> 2;
    const int q0 = qt * 64;
    const int qw0 = q0 + w * 16;
    const float scale = 0.08838834764831845f / fmaxf(fabsf(tptr[0]), 1e-6f);
    const float sl = scale * 1.4426950408889634f;

    const uint32_t sQ = sb;

    const __half* qfg = g_qf + ((size_t)(b * SEQ) + q0) * DMODEL + h * DHEAD;
    const __half* kfg = g_kf + (size_t)(b * SEQ) * NKVD + kv * DHEAD;
    const __half* vg  = g_vf + (size_t)(b * SEQ) * NKVD + kv * DHEAD;

    const int nkt = qt + 1;

    // prologue: Q (64 rows) + kv stage 0, then kv stage 1 (if any)
    {
#pragma unroll
        for (int i = 0; i < 8; i++) {
            int chunk = tid + i * AT_T;
            int row = chunk >> 4, cc = chunk & 15;
            const void* gp = (const char*)qfg + ((size_t)row * DMODEL + cc * 8) * 2;
            uint32_t sp = sQ + (cc >> 3) * 8192 + SWZ128(row * 128 + (cc & 7) * 16);
            asm volatile("cp.async.cg.shared.global [%0], [%1], 16;"
                         :: "r"(sp), "l"(gp));
        }
        attn_issue_kv(sb + AT_STAGE0, kfg, vg, 0, tid);
        if (nkt > 1)
            attn_issue_kv(sb + AT_STAGE0 + AT_STAGEB, kfg, vg, 64, tid);
    }

    const int a_row_l = (l & 7) + (l & 8);
    const int a_col_l = ((l >> 4) & 1) * 16;
    const int b_row_l = (l & 7) + ((l >> 4) & 1) * 8;
    const int b_col_l = ((l >> 3) & 1) * 16;
    const int v_row_l = (l & 7) + ((l >> 3) & 1) * 8;
    const int v_col_l = ((l >> 4) & 1) * 16;

    float oacc[16][4];
    float lacc[4] = {0.f, 0.f, 0.f, 0.f};
#pragma unroll
    for (int i = 0; i < 16; i++)
#pragma unroll
        for (int f = 0; f < 4; f++) oacc[i][f] = 0.f;
    float m0 = -3.0e38f, m1 = -3.0e38f;

    for (int kt = 0; kt < nkt; kt++) {
        if (kt + 1 < nkt) {
            asm volatile("cp.async.wait_group 1;" ::: "memory");
        } else {
            asm volatile("cp.async.wait_group 0;" ::: "memory");
        }
        __syncthreads();
        if (kt + 2 < nkt)
            attn_issue_kv(sb + AT_STAGE0 + ((kt + 2) % 3) * AT_STAGEB,
                          kfg, vg, (kt + 2) * 64, tid);

        const int k0 = kt * 64;
        const uint32_t st = sb + AT_STAGE0 + (kt % 3) * AT_STAGEB;

        if (k0 <= qw0 + 15) {
            float sacc[8][4];
#pragma unroll
            for (int i = 0; i < 8; i++)
#pragma unroll
                for (int f = 0; f < 4; f++) sacc[i][f] = 0.f;

#pragma unroll
            for (int ks = 0; ks < 8; ks++) {
                uint32_t qoff = (ks >> 2) * 8192 +
                    SWZ128((w * 16 + a_row_l) * 128 + (ks & 3) * 32 + a_col_l);
                uint32_t qa[4];
                ldsm4(qa[0], qa[1], qa[2], qa[3], sQ + qoff);
#pragma unroll
                for (int np = 0; np < 4; np++) {
                    uint32_t koff = st + (ks >> 2) * 8192 +
                        SWZ128((np * 16 + b_row_l) * 128 + (ks & 3) * 32 + b_col_l);
                    uint32_t kf4[4];
                    ldsm4(kf4[0], kf4[1], kf4[2], kf4[3], koff);
                    mma16816h(sacc[2 * np],     qa[0], qa[1], qa[2], qa[3], kf4[0], kf4[1]);
                    mma16816h(sacc[2 * np + 1], qa[0], qa[1], qa[2], qa[3], kf4[2], kf4[3]);
                }
            }

            if (k0 + 63 > qw0) {
                int qa0 = qw0 + (l >> 2), qa1 = qa0 + 8;
                int kc0 = k0 + 2 * (l & 3);
#pragma unroll
                for (int nt = 0; nt < 8; nt++) {
                    int kc = kc0 + nt * 8;
                    if (kc     > qa0) sacc[nt][0] = -3.0e38f;
                    if (kc + 1 > qa0) sacc[nt][1] = -3.0e38f;
                    if (kc     > qa1) sacc[nt][2] = -3.0e38f;
                    if (kc + 1 > qa1) sacc[nt][3] = -3.0e38f;
                }
            }

            float mx0 = -3.0e38f, mx1 = -3.0e38f;
#pragma unroll
            for (int nt = 0; nt < 8; nt++) {
                mx0 = fmaxf(mx0, fmaxf(sacc[nt][0], sacc[nt][1]));
                mx1 = fmaxf(mx1, fmaxf(sacc[nt][2], sacc[nt][3]));
            }
            mx0 = fmaxf(mx0, __shfl_xor_sync(0xffffffffu, mx0, 1));
            mx0 = fmaxf(mx0, __shfl_xor_sync(0xffffffffu, mx0, 2));
            mx1 = fmaxf(mx1, __shfl_xor_sync(0xffffffffu, mx1, 1));
            mx1 = fmaxf(mx1, __shfl_xor_sync(0xffffffffu, mx1, 2));
            float mn0 = fmaxf(m0, mx0), mn1 = fmaxf(m1, mx1);
            bool ch = (mn0 > m0) || (mn1 > m1);
            if (__any_sync(0xffffffffu, ch)) {
                float a0 = exp2f((m0 - mn0) * sl);
                float a1 = exp2f((m1 - mn1) * sl);
#pragma unroll
                for (int nt = 0; nt < 16; nt++) {
                    oacc[nt][0] *= a0; oacc[nt][1] *= a0;
                    oacc[nt][2] *= a1; oacc[nt][3] *= a1;
                }
                lacc[0] *= a0; lacc[1] *= a0; lacc[2] *= a1; lacc[3] *= a1;
            }
            m0 = mn0; m1 = mn1;
            const float bb0 = mn0 * sl, bb1 = mn1 * sl;

            uint32_t pp[8][2];
#pragma unroll
            for (int nt = 0; nt < 8; nt++) {
                float t0 = fmaf(sacc[nt][0], sl, -bb0);
                float t1 = fmaf(sacc[nt][1], sl, -bb0);
                float t2 = fmaf(sacc[nt][2], sl, -bb1);
                float t3 = fmaf(sacc[nt][3], sl, -bb1);
                pp[nt][0] = exp2_f16x2(packf16(t1, t0));
                pp[nt][1] = exp2_f16x2(packf16(t3, t2));
            }

#pragma unroll
            for (int ks = 0; ks < 4; ks++) {
                uint32_t pa0 = pp[2 * ks][0], pa1 = pp[2 * ks][1];
                uint32_t pa2 = pp[2 * ks + 1][0], pa3 = pp[2 * ks + 1][1];
                mma16816h(lacc, pa0, pa1, pa2, pa3, 0x3C003C00u, 0x3C003C00u);
#pragma unroll
                for (int jp = 0; jp < 8; jp++) {
                    uint32_t voff = st + 16384 + (jp >> 2) * 8192 +
                        SWZ128((ks * 16 + v_row_l) * 128 + (jp & 3) * 32 + v_col_l);
                    uint32_t v4[4];
                    ldsm4t(v4[0], v4[1], v4[2], v4[3], voff);
                    mma16816h(oacc[2 * jp],     pa0, pa1, pa2, pa3, v4[0], v4[1]);
                    mma16816h(oacc[2 * jp + 1], pa0, pa1, pa2, pa3, v4[2], v4[3]);
                }
            }
        }
    }

    // epilogue: normalize + single f16 store
    const float inv0 = 1.0f / lacc[0];
    const float inv1 = 1.0f / lacc[2];
    const size_t r0g = (size_t)(b * SEQ) + qw0 + (l >> 2);
    const size_t r1g = r0g + 8;
#pragma unroll
    for (int nt = 0; nt < 16; nt++) {
        int col = h * DHEAD + nt * 8 + 2 * (l & 3);
        *(__half2*)(g_of + r0g * DMODEL + col) =
            __floats2half2_rn(oacc[nt][0] * inv0, oacc[nt][1] * inv0);
        *(__half2*)(g_of + r1g * DMODEL + col) =
            __floats2half2_rn(oacc[nt][2] * inv1, oacc[nt][3] * inv1);
    }
}

// ---------------------------------------------------------------------------
extern "C" void kernel_launch(void* const* d_in, const int* in_sizes, int n_in,
                              void* d_out, int out_size)
{
    const float* x  = (const float*)d_in[0];
    const float* wq = (const float*)d_in[1];
    const float* wk = (const float*)d_in[2];
    const float* wv = (const float*)d_in[3];
    const float* wo = (const float*)d_in[4];
    const float* tp = (const float*)d_in[5];
    float* out = (float*)d_out;

    __half *xf, *of, *wqkv, *wof;
    cudaGetSymbolAddress((void**)&xf, g_xf);
    cudaGetSymbolAddress((void**)&of, g_of);
    cudaGetSymbolAddress((void**)&wqkv, g_wqkv);
    cudaGetSymbolAddress((void**)&wof, g_wof);

    cudaFuncSetAttribute(qkv_gemm_kernel, cudaFuncAttributeMaxDynamicSharedMemorySize, GSMEM3);
    cudaFuncSetAttribute(oproj_gemm_kernel, cudaFuncAttributeMaxDynamicSharedMemorySize, GSMEM3);
    cudaFuncSetAttribute(hmma_attn_kernel, cudaFuncAttributeMaxDynamicSharedMemorySize, AT_SMEM);

    // converters + rope table
    rope_table_kernel<<<(SEQ * 64 + 255) / 256, 256>>>();
    {
        int n4 = MTOT * DMODEL / 4;
        f16conv_kernel<<<(n4 + 255) / 256, 256>>>((const float4*)x, (__half2*)xf, n4);
        wconv_kernel<<<dim3(DMODEL / 32, DMODEL / 32, 4), dim3(32, 8)>>>(
            wq, wk, wv, wo, wqkv, wof);
    }

    // fused QKV projection + RoPE (grid form, 2 CTAs/SM)
    qkv_gemm_kernel<<<dim3(NQKV / 128, MTOT / 128), GT, GSMEM3>>>(xf, wqkv);

    // flash attention (64-q CTAs, 2 CTAs/SM)
    hmma_attn_kernel<<<dim3(SEQ / 64, NHEADS, BATCH), AT_T, AT_SMEM>>>(tp);

    // output projection (grid form, 2 CTAs/SM)
    oproj_gemm_kernel<<<dim3(DMODEL / 128, MTOT / 128), GT, GSMEM3>>>(of, wof, out);
}